// round 3
// baseline (speedup 1.0000x reference)
#include <cuda_runtime.h>
#include <cuda_bf16.h>
#include <cstdint>

// Quantized int8 3x3 VALID conv via tensor-core implicit GEMM (mma.sync s8).
// x: [64,16,256,256] int32 (int8 values), w: [16,16,3,3] int32, bias: [16] f32
// out: [64,16,254,254] f32
//
// out = 1e-4 * ( Sum x*w - 3*Sum_window(x) - 7*Sum(w) + 21*144 ) + bq[co]
// bq = rint(bias/1e-4)*1e-4 (clamped). Integer math exact via IMMA.
// Window sum Sum_window(x) computed as an extra "ones" B column (N-group 2).

#define CIN 16
#define COUT 16
#define HIN 256
#define WIN 256
#define HOUT 254
#define WOUT 254
#define TH 16
#define TW 64
#define ROWS 18
#define COLS 68                 // 66 needed, padded to multiple of 4
#define NQUADS (4 * ROWS * 17)  // packer work items

// Precomputed B fragments (per lane) for mma.m16n8k32 / m16n8k16, s8.
// Index layout: idx = kh*3 + g  (g: 0 = couts 0-7, 1 = couts 8-15, 2 = ones col)
__device__ unsigned g_b32[9 * 2 * 32];  // [idx][reg 0/1][lane]
__device__ unsigned g_b16[9 * 32];      // [idx][lane]
__device__ int   g_wc[COUT];            // -7*Sum(w) + 21*144
__device__ float g_bq[COUT];

__global__ void prep_kernel(const int* __restrict__ w, const float* __restrict__ bias) {
    int t = threadIdx.x;
    if (t < 288) {
        int lane = t & 31, idx = t >> 5;       // idx 0..8
        int kh = idx / 3, g = idx - kh * 3;
        int n  = lane >> 2;                     // B col within group
        int kb = (lane & 3) << 2;               // starting k row
        unsigned b0 = 0, b1 = 0, bk = 0;
        #pragma unroll
        for (int i = 0; i < 4; i++) {
            int ci = kb + i;                    // 0..15
            int v0, v1, v2;
            if (g == 2) {
                v0 = (n == 0) ? 1 : 0; v1 = v0; v2 = v0;
            } else {
                int co = g * 8 + n;
                v0 = w[(co * CIN + ci) * 9 + kh * 3 + 0];   // k32 rows 0-15  -> tap kw0
                v1 = w[(co * CIN + ci) * 9 + kh * 3 + 1];   // k32 rows 16-31 -> tap kw1
                v2 = w[(co * CIN + ci) * 9 + kh * 3 + 2];   // k16            -> tap kw2
            }
            b0 |= (unsigned)(v0 & 0xFF) << (8 * i);
            b1 |= (unsigned)(v1 & 0xFF) << (8 * i);
            bk |= (unsigned)(v2 & 0xFF) << (8 * i);
        }
        g_b32[(idx * 2 + 0) * 32 + lane] = b0;
        g_b32[(idx * 2 + 1) * 32 + lane] = b1;
        g_b16[idx * 32 + lane] = bk;
    }
    if (t < COUT) {
        int s = 0;
        #pragma unroll 4
        for (int k = 0; k < CIN * 9; k++) s += w[t * CIN * 9 + k];
        g_wc[t] = -7 * s + 21 * CIN * 9;
        float b = bias[t];
        float r = rintf(b / 0.0001f);
        r = fminf(fmaxf(r, -2147483648.0f), 2147483647.0f);
        g_bq[t] = r * 0.0001f;
    }
}

__device__ __forceinline__ unsigned pack4(int a, int b, int c, int d) {
    unsigned t = __byte_perm((unsigned)a, (unsigned)b, 0x0040);
    unsigned u = __byte_perm((unsigned)c, (unsigned)d, 0x4000);
    return __byte_perm(t, u, 0x7610);
}

__device__ __forceinline__ void ldm4(unsigned a[4], unsigned addr) {
    asm volatile("ldmatrix.sync.aligned.m8n8.x4.shared.b16 {%0,%1,%2,%3},[%4];"
                 : "=r"(a[0]), "=r"(a[1]), "=r"(a[2]), "=r"(a[3]) : "r"(addr));
}
__device__ __forceinline__ void ldm2(unsigned a[2], unsigned addr) {
    asm volatile("ldmatrix.sync.aligned.m8n8.x2.shared.b16 {%0,%1},[%2];"
                 : "=r"(a[0]), "=r"(a[1]) : "r"(addr));
}
__device__ __forceinline__ void mma32(int c[4], const unsigned a[4], unsigned b0, unsigned b1) {
    asm volatile("mma.sync.aligned.m16n8k32.row.col.s32.s8.s8.s32 "
                 "{%0,%1,%2,%3},{%4,%5,%6,%7},{%8,%9},{%0,%1,%2,%3};"
                 : "+r"(c[0]), "+r"(c[1]), "+r"(c[2]), "+r"(c[3])
                 : "r"(a[0]), "r"(a[1]), "r"(a[2]), "r"(a[3]), "r"(b0), "r"(b1));
}
__device__ __forceinline__ void mma16(int c[4], const unsigned a[2], unsigned b0) {
    asm volatile("mma.sync.aligned.m16n8k16.row.col.s32.s8.s8.s32 "
                 "{%0,%1,%2,%3},{%4,%5},{%6},{%0,%1,%2,%3};"
                 : "+r"(c[0]), "+r"(c[1]), "+r"(c[2]), "+r"(c[3])
                 : "r"(a[0]), "r"(a[1]), "r"(b0));
}

__global__ void __launch_bounds__(256, 2)
conv_kernel(const int* __restrict__ inp, float* __restrict__ out) {
    // Input tile, int8 packed, cin-contiguous: pixel (r,c) occupies 16 bytes at
    // sx[(r*COLS + c)*4 .. +3]  (words = cin quads 0..3)
    __shared__ __align__(16) unsigned sx[ROWS * COLS * 4];
    __shared__ int   swc[COUT];
    __shared__ float sbq[COUT];

    const int tid  = threadIdx.x;
    const int lane = tid & 31;
    const int wid  = tid >> 5;
    const int n    = blockIdx.z;
    const int oh0  = blockIdx.y * TH;
    const int ow0  = blockIdx.x * TW;

    const int* xin = inp + (size_t)n * CIN * HIN * WIN;

    // ---- pack input tile: int32 -> int8, [cin-plane] -> [pixel][cin] ----
    for (int gi = tid; gi < NQUADS; gi += 256) {
        int g   = gi / (ROWS * 17);
        int rem = gi - g * (ROWS * 17);
        int r   = rem / 17;
        int c4  = (rem - r * 17) * 4;
        int ih = oh0 + r, iw = ow0 + c4;
        unsigned p0, p1, p2, p3;
        const int* base = xin + (size_t)(4 * g) * (HIN * WIN) + ih * WIN + iw;
        if (ih < HIN && iw + 3 < WIN) {
            int4 v0 = *(const int4*)(base);
            int4 v1 = *(const int4*)(base + HIN * WIN);
            int4 v2 = *(const int4*)(base + 2 * HIN * WIN);
            int4 v3 = *(const int4*)(base + 3 * HIN * WIN);
            p0 = pack4(v0.x, v1.x, v2.x, v3.x);
            p1 = pack4(v0.y, v1.y, v2.y, v3.y);
            p2 = pack4(v0.z, v1.z, v2.z, v3.z);
            p3 = pack4(v0.w, v1.w, v2.w, v3.w);
        } else {
            unsigned t[4];
            #pragma unroll
            for (int j = 0; j < 4; j++) {
                t[j] = 0;
                if (ih < HIN && iw + j < WIN) {
                    int v0 = base[j];
                    int v1 = base[j + HIN * WIN];
                    int v2 = base[j + 2 * HIN * WIN];
                    int v3 = base[j + 3 * HIN * WIN];
                    t[j] = pack4(v0, v1, v2, v3);
                }
            }
            p0 = t[0]; p1 = t[1]; p2 = t[2]; p3 = t[3];
        }
        unsigned* dst = &sx[(r * COLS + c4) * 4 + g];
        dst[0] = p0; dst[4] = p1; dst[8] = p2; dst[12] = p3;
    }
    if (tid < COUT) { swc[tid] = g_wc[tid]; sbq[tid] = g_bq[tid]; }

    // ---- load B fragments (per lane, registers) ----
    unsigned b32r[3][3][2], b16r[3][3];
    #pragma unroll
    for (int kh = 0; kh < 3; kh++)
        #pragma unroll
        for (int g = 0; g < 3; g++) {
            int idx = kh * 3 + g;
            b32r[kh][g][0] = g_b32[(idx * 2 + 0) * 32 + lane];
            b32r[kh][g][1] = g_b32[(idx * 2 + 1) * 32 + lane];
            b16r[kh][g]    = g_b16[idx * 32 + lane];
        }
    __syncthreads();

    // Per-lane epilogue constants
    const int q    = lane & 3;
    const int prow = lane >> 2;
    const int wc0 = swc[2 * q],     wc1 = swc[2 * q + 1];
    const int wc2 = swc[8 + 2 * q], wc3 = swc[9 + 2 * q];
    const float bq0 = sbq[2 * q],     bq1 = sbq[2 * q + 1];
    const float bq2 = sbq[8 + 2 * q], bq3 = sbq[9 + 2 * q];

    const unsigned sxa = (unsigned)__cvta_generic_to_shared(sx);
    const unsigned off32 = (unsigned)((lane & 15) * 16 + (lane & 16));  // px + (kw0/kw1)
    const unsigned off16 = (unsigned)(((lane & 15) + 2) * 16);          // px + kw2

    const size_t cs = (size_t)HOUT * WOUT;
    float* obase = out + (size_t)(n * COUT) * cs;

    // ---- 64 pixel-tiles (16 px each); warp w handles tiles w, w+8, ... ----
    #pragma unroll 1
    for (int tt = wid; tt < 64; tt += 8) {
        const int r  = tt >> 2;
        const int c0 = (tt & 3) << 4;

        int acc0[4] = {0, 0, 0, 0};
        int acc1[4] = {0, 0, 0, 0};
        int acc2[4] = {0, 0, 0, 0};

        #pragma unroll
        for (int kh = 0; kh < 3; kh++) {
            unsigned rowaddr = sxa + (unsigned)(((r + kh) * COLS + c0) * 16);
            unsigned a[4], a2[2];
            ldm4(a,  rowaddr + off32);
            ldm2(a2, rowaddr + off16);
            mma32(acc0, a, b32r[kh][0][0], b32r[kh][0][1]);
            mma32(acc1, a, b32r[kh][1][0], b32r[kh][1][1]);
            mma32(acc2, a, b32r[kh][2][0], b32r[kh][2][1]);
            mma16(acc0, a2, b16r[kh][0]);
            mma16(acc1, a2, b16r[kh][1]);
            mma16(acc2, a2, b16r[kh][2]);
        }

        // window sums live in col 0 of group 2 (quad leader's c0/c2)
        int ws0 = __shfl_sync(0xffffffffu, acc2[0], lane & ~3);
        int ws1 = __shfl_sync(0xffffffffu, acc2[2], lane & ~3);

        const int oh = oh0 + r;
        if (oh < HOUT) {
            float* ob = obase + (size_t)oh * WOUT;
            int px0 = ow0 + c0 + prow;
            int px1 = px0 + 8;
            if (px0 < WOUT) {
                ob[(size_t)(2 * q)     * cs + px0] = fmaf((float)(acc0[0] - 3 * ws0 + wc0), 1e-4f, bq0);
                ob[(size_t)(2 * q + 1) * cs + px0] = fmaf((float)(acc0[1] - 3 * ws0 + wc1), 1e-4f, bq1);
                ob[(size_t)(8 + 2 * q) * cs + px0] = fmaf((float)(acc1[0] - 3 * ws0 + wc2), 1e-4f, bq2);
                ob[(size_t)(9 + 2 * q) * cs + px0] = fmaf((float)(acc1[1] - 3 * ws0 + wc3), 1e-4f, bq3);
            }
            if (px1 < WOUT) {
                ob[(size_t)(2 * q)     * cs + px1] = fmaf((float)(acc0[2] - 3 * ws1 + wc0), 1e-4f, bq0);
                ob[(size_t)(2 * q + 1) * cs + px1] = fmaf((float)(acc0[3] - 3 * ws1 + wc1), 1e-4f, bq1);
                ob[(size_t)(8 + 2 * q) * cs + px1] = fmaf((float)(acc1[2] - 3 * ws1 + wc2), 1e-4f, bq2);
                ob[(size_t)(9 + 2 * q) * cs + px1] = fmaf((float)(acc1[3] - 3 * ws1 + wc3), 1e-4f, bq3);
            }
        }
    }
}

extern "C" void kernel_launch(void* const* d_in, const int* in_sizes, int n_in,
                              void* d_out, int out_size) {
    const int*   x    = (const int*)d_in[0];
    const int*   w    = (const int*)d_in[1];
    const float* bias = (const float*)d_in[2];
    float* outp = (float*)d_out;

    prep_kernel<<<1, 288>>>(w, bias);

    dim3 grid((WOUT + TW - 1) / TW,   // 4
              (HOUT + TH - 1) / TH,   // 16
              64);                    // batch
    conv_kernel<<<grid, 256>>>(x, outp);
}

// round 4
// speedup vs baseline: 1.6553x; 1.6553x over previous
#include <cuda_runtime.h>
#include <cuda_bf16.h>
#include <cstdint>

// Quantized int8 3x3 VALID conv via tensor-core implicit GEMM (mma.sync s8),
// minimal-issue formulation: 10 mma per 16-pixel tile (floor for N=16),
// window sum on the fma pipe via dp4a over the A fragments.
//
// x: [64,16,256,256] int32 (int8 values), w: [16,16,3,3] int32, bias: [16] f32
// out: [64,16,254,254] f32
// out = 1e-4*( Sum x*w - 3*Wsum(x) - 7*Sum(w) + 21*144 ) + bq[co], exact int math.

#define CIN 16
#define COUT 16
#define HIN 256
#define WIN 256
#define HOUT 254
#define WOUT 254
#define TH 16
#define TW 64
#define ROWS 18
#define COLS 68
#define NQUADS (4 * ROWS * 17)

// B fragments. Tap order t = kh*3+kw (0..8). mma j (0..3) covers taps (2j, 2j+1)
// as k rows 0-15 / 16-31; mma16 covers tap 8.
__device__ unsigned g_bfrag[2][4][2][32];  // [group][mma j][reg h][lane]
__device__ unsigned g_bk[2][32];           // [group][lane]
__device__ int   g_wc[COUT];               // -7*Sum(w) + 21*144
__device__ float g_bq[COUT];

__global__ void prep_kernel(const int* __restrict__ w, const float* __restrict__ bias) {
    int t = threadIdx.x;
    if (t < 512) {
        int lane = t & 31;
        int rem  = t >> 5;          // 0..15
        int g = rem >> 3;           // group
        int j = (rem >> 1) & 3;     // mma index
        int h = rem & 1;            // b-reg
        int tap = 2 * j + h;
        int co = g * 8 + (lane >> 2);
        int cb = (lane & 3) << 2;
        unsigned pk = 0;
        #pragma unroll
        for (int i = 0; i < 4; i++)
            pk |= (unsigned)(w[(co * CIN + cb + i) * 9 + tap] & 0xFF) << (8 * i);
        g_bfrag[g][j][h][lane] = pk;
        if (h == 0 && j == 0) {     // also fill k16 fragment (tap 8)
            unsigned qk = 0;
            #pragma unroll
            for (int i = 0; i < 4; i++)
                qk |= (unsigned)(w[(co * CIN + cb + i) * 9 + 8] & 0xFF) << (8 * i);
            g_bk[g][lane] = qk;
        }
    }
    if (t < COUT) {
        int s = 0;
        #pragma unroll 4
        for (int k = 0; k < CIN * 9; k++) s += w[t * CIN * 9 + k];
        g_wc[t] = -7 * s + 21 * CIN * 9;
        float b = bias[t];
        float r = rintf(b / 0.0001f);
        r = fminf(fmaxf(r, -2147483648.0f), 2147483647.0f);
        g_bq[t] = r * 0.0001f;
    }
}

__device__ __forceinline__ unsigned pack4(int a, int b, int c, int d) {
    unsigned t = __byte_perm((unsigned)a, (unsigned)b, 0x0040);
    unsigned u = __byte_perm((unsigned)c, (unsigned)d, 0x4000);
    return __byte_perm(t, u, 0x7610);
}
__device__ __forceinline__ void ldm4(unsigned a[4], unsigned addr) {
    asm volatile("ldmatrix.sync.aligned.m8n8.x4.shared.b16 {%0,%1,%2,%3},[%4];"
                 : "=r"(a[0]), "=r"(a[1]), "=r"(a[2]), "=r"(a[3]) : "r"(addr));
}
__device__ __forceinline__ void ldm2(unsigned a[2], unsigned addr) {
    asm volatile("ldmatrix.sync.aligned.m8n8.x2.shared.b16 {%0,%1},[%2];"
                 : "=r"(a[0]), "=r"(a[1]) : "r"(addr));
}
__device__ __forceinline__ void mma32(int c[4], const unsigned a[4], unsigned b0, unsigned b1) {
    asm volatile("mma.sync.aligned.m16n8k32.row.col.s32.s8.s8.s32 "
                 "{%0,%1,%2,%3},{%4,%5,%6,%7},{%8,%9},{%0,%1,%2,%3};"
                 : "+r"(c[0]), "+r"(c[1]), "+r"(c[2]), "+r"(c[3])
                 : "r"(a[0]), "r"(a[1]), "r"(a[2]), "r"(a[3]), "r"(b0), "r"(b1));
}
__device__ __forceinline__ void mma16(int c[4], const unsigned a[2], unsigned b0) {
    asm volatile("mma.sync.aligned.m16n8k16.row.col.s32.s8.s8.s32 "
                 "{%0,%1,%2,%3},{%4,%5},{%6},{%0,%1,%2,%3};"
                 : "+r"(c[0]), "+r"(c[1]), "+r"(c[2]), "+r"(c[3])
                 : "r"(a[0]), "r"(a[1]), "r"(b0));
}

__global__ void __launch_bounds__(256, 2)
conv_kernel(const int* __restrict__ inp, float* __restrict__ out) {
    // int8 tile, cin-contiguous: pixel (r,c) = 16 bytes at sx[(r*COLS+c)*4 ..]
    __shared__ __align__(16) unsigned sx[ROWS * COLS * 4];
    __shared__ int   swc[COUT];
    __shared__ float sbq[COUT];

    const int tid  = threadIdx.x;
    const int lane = tid & 31;
    const int wid  = tid >> 5;
    const int n    = blockIdx.z;
    const int oh0  = blockIdx.y * TH;
    const int ow0  = blockIdx.x * TW;

    const int* xin = inp + (size_t)n * CIN * HIN * WIN;

    // ---- pack input tile: int32 -> int8, planes -> pixel-contiguous ----
    for (int gi = tid; gi < NQUADS; gi += 256) {
        int g   = gi / (ROWS * 17);
        int rem = gi - g * (ROWS * 17);
        int r   = rem / 17;
        int c4  = (rem - r * 17) * 4;
        int ih = oh0 + r, iw = ow0 + c4;
        unsigned p0, p1, p2, p3;
        const int* base = xin + (size_t)(4 * g) * (HIN * WIN) + ih * WIN + iw;
        if (ih < HIN && iw + 3 < WIN) {
            int4 v0 = *(const int4*)(base);
            int4 v1 = *(const int4*)(base + HIN * WIN);
            int4 v2 = *(const int4*)(base + 2 * HIN * WIN);
            int4 v3 = *(const int4*)(base + 3 * HIN * WIN);
            p0 = pack4(v0.x, v1.x, v2.x, v3.x);
            p1 = pack4(v0.y, v1.y, v2.y, v3.y);
            p2 = pack4(v0.z, v1.z, v2.z, v3.z);
            p3 = pack4(v0.w, v1.w, v2.w, v3.w);
        } else {
            unsigned t[4];
            #pragma unroll
            for (int j = 0; j < 4; j++) {
                t[j] = 0;
                if (ih < HIN && iw + j < WIN) {
                    int v0 = base[j];
                    int v1 = base[j + HIN * WIN];
                    int v2 = base[j + 2 * HIN * WIN];
                    int v3 = base[j + 3 * HIN * WIN];
                    t[j] = pack4(v0, v1, v2, v3);
                }
            }
            p0 = t[0]; p1 = t[1]; p2 = t[2]; p3 = t[3];
        }
        unsigned* dst = &sx[(r * COLS + c4) * 4 + g];
        dst[0] = p0; dst[4] = p1; dst[8] = p2; dst[12] = p3;
    }
    if (tid < COUT) { swc[tid] = g_wc[tid]; sbq[tid] = g_bq[tid]; }

    // ---- B fragments into registers ----
    unsigned bf[2][4][2], bk2[2];
    #pragma unroll
    for (int g = 0; g < 2; g++) {
        #pragma unroll
        for (int j = 0; j < 4; j++) {
            bf[g][j][0] = g_bfrag[g][j][0][lane];
            bf[g][j][1] = g_bfrag[g][j][1][lane];
        }
        bk2[g] = g_bk[g][lane];
    }
    __syncthreads();

    // Per-lane A-address tap offsets: mma j, this lane's half (lo: tap 2j, hi: 2j+1)
    const int hi = lane >> 4;
    unsigned toff[4];
    #pragma unroll
    for (int j = 0; j < 4; j++) {
        int t = 2 * j + hi;
        toff[j] = (unsigned)(((t / 3) * COLS + (t % 3)) * 16);
    }
    const unsigned toff4 = (unsigned)((2 * COLS + 2) * 16);

    const int q    = lane & 3;
    const int prow = lane >> 2;
    const int wc0 = swc[2 * q],     wc1 = swc[2 * q + 1];
    const int wc2 = swc[8 + 2 * q], wc3 = swc[9 + 2 * q];
    const float bq0 = sbq[2 * q],     bq1 = sbq[2 * q + 1];
    const float bq2 = sbq[8 + 2 * q], bq3 = sbq[9 + 2 * q];

    const unsigned sxa = (unsigned)__cvta_generic_to_shared(sx);
    const size_t cs = (size_t)HOUT * WOUT;
    float* obase = out + (size_t)(n * COUT) * cs;

    // ---- 64 pixel-tiles (16 px each); warp w handles tiles w, w+8, ... ----
    #pragma unroll 1
    for (int tt = wid; tt < 64; tt += 8) {
        const int r  = tt >> 2;
        const int c0 = (tt & 3) << 4;
        const unsigned tilebase = sxa + (unsigned)(((r * COLS + c0 + (lane & 15)) * 16));

        unsigned a[4][4], a5[2];
        #pragma unroll
        for (int j = 0; j < 4; j++) ldm4(a[j], tilebase + toff[j]);
        ldm2(a5, tilebase + toff4);

        int acc0[4] = {0, 0, 0, 0};
        int acc1[4] = {0, 0, 0, 0};
        #pragma unroll
        for (int j = 0; j < 4; j++) {
            mma32(acc0, a[j], bf[0][j][0], bf[0][j][1]);
            mma32(acc1, a[j], bf[1][j][0], bf[1][j][1]);
        }
        mma16(acc0, a5, bk2[0]);
        mma16(acc1, a5, bk2[1]);

        // window sums on fma pipe: ones-dot over A fragments, quad-reduced
        int s_lo = 0, s_hi = 0;
        #pragma unroll
        for (int j = 0; j < 4; j++) {
            s_lo = __dp4a((int)a[j][0], 0x01010101, s_lo);
            s_hi = __dp4a((int)a[j][1], 0x01010101, s_hi);
            s_lo = __dp4a((int)a[j][2], 0x01010101, s_lo);
            s_hi = __dp4a((int)a[j][3], 0x01010101, s_hi);
        }
        s_lo = __dp4a((int)a5[0], 0x01010101, s_lo);
        s_hi = __dp4a((int)a5[1], 0x01010101, s_hi);
        s_lo += __shfl_xor_sync(0xffffffffu, s_lo, 1);
        s_lo += __shfl_xor_sync(0xffffffffu, s_lo, 2);
        s_hi += __shfl_xor_sync(0xffffffffu, s_hi, 1);
        s_hi += __shfl_xor_sync(0xffffffffu, s_hi, 2);

        const int oh = oh0 + r;
        if (oh < HOUT) {
            float* ob = obase + (size_t)oh * WOUT;
            int px0 = ow0 + c0 + prow;
            int px1 = px0 + 8;
            if (px0 < WOUT) {
                ob[(size_t)(2 * q)     * cs + px0] = fmaf((float)(acc0[0] - 3 * s_lo + wc0), 1e-4f, bq0);
                ob[(size_t)(2 * q + 1) * cs + px0] = fmaf((float)(acc0[1] - 3 * s_lo + wc1), 1e-4f, bq1);
                ob[(size_t)(8 + 2 * q) * cs + px0] = fmaf((float)(acc1[0] - 3 * s_lo + wc2), 1e-4f, bq2);
                ob[(size_t)(9 + 2 * q) * cs + px0] = fmaf((float)(acc1[1] - 3 * s_lo + wc3), 1e-4f, bq3);
            }
            if (px1 < WOUT) {
                ob[(size_t)(2 * q)     * cs + px1] = fmaf((float)(acc0[2] - 3 * s_hi + wc0), 1e-4f, bq0);
                ob[(size_t)(2 * q + 1) * cs + px1] = fmaf((float)(acc0[3] - 3 * s_hi + wc1), 1e-4f, bq1);
                ob[(size_t)(8 + 2 * q) * cs + px1] = fmaf((float)(acc1[2] - 3 * s_hi + wc2), 1e-4f, bq2);
                ob[(size_t)(9 + 2 * q) * cs + px1] = fmaf((float)(acc1[3] - 3 * s_hi + wc3), 1e-4f, bq3);
            }
        }
    }
}

extern "C" void kernel_launch(void* const* d_in, const int* in_sizes, int n_in,
                              void* d_out, int out_size) {
    const int*   x    = (const int*)d_in[0];
    const int*   w    = (const int*)d_in[1];
    const float* bias = (const float*)d_in[2];
    float* outp = (float*)d_out;

    prep_kernel<<<1, 512>>>(w, bias);

    dim3 grid((WOUT + TW - 1) / TW,   // 4
              (HOUT + TH - 1) / TH,   // 16
              64);                    // batch
    conv_kernel<<<grid, 256>>>(x, outp);
}